// round 1
// baseline (speedup 1.0000x reference)
#include <cuda_runtime.h>

#define SEQL 2048
#define NB   4
#define DM   768
#define MTOT (NB * SEQL)

#define BM 128
#define BN 128
#define BK 8
#define PAD 132   // 128 + 4: conflict-free transposed stores, keeps 16B alignment

// Scratch (static __device__ globals: allowed; no runtime allocation)
__device__ float g_Q[(size_t)MTOT * DM];
__device__ float g_K[(size_t)MTOT * DM];
__device__ float g_V[(size_t)MTOT * DM];
__device__ float g_S[(size_t)NB * SEQL * SEQL];

// ---------------------------------------------------------------------------
// NT tile GEMM: C[128,128] += A(rows m, K contiguous) . B(rows n, K contiguous)
// 256 threads, each computes an 8x8 micro-tile.
// ---------------------------------------------------------------------------
__device__ __forceinline__ void gemm_tile_nt(
    const float* __restrict__ A, int lda,
    const float* __restrict__ B, int ldb,
    int Kdim, float c[8][8])
{
    __shared__ float As[BK][PAD];
    __shared__ float Bs[BK][PAD];
    const int tid = threadIdx.x;
    const int row = tid >> 1;          // 0..127
    const int vec = (tid & 1) * 4;     // 0 or 4
    const int tx  = tid & 15;
    const int ty  = tid >> 4;

    for (int k0 = 0; k0 < Kdim; k0 += BK) {
        float4 av = *reinterpret_cast<const float4*>(A + (size_t)row * lda + k0 + vec);
        float4 bv = *reinterpret_cast<const float4*>(B + (size_t)row * ldb + k0 + vec);
        __syncthreads();
        As[vec + 0][row] = av.x; As[vec + 1][row] = av.y;
        As[vec + 2][row] = av.z; As[vec + 3][row] = av.w;
        Bs[vec + 0][row] = bv.x; Bs[vec + 1][row] = bv.y;
        Bs[vec + 2][row] = bv.z; Bs[vec + 3][row] = bv.w;
        __syncthreads();
        #pragma unroll
        for (int kk = 0; kk < BK; kk++) {
            float a[8], b[8];
            *reinterpret_cast<float4*>(a)     = *reinterpret_cast<const float4*>(&As[kk][ty * 8]);
            *reinterpret_cast<float4*>(a + 4) = *reinterpret_cast<const float4*>(&As[kk][ty * 8 + 4]);
            *reinterpret_cast<float4*>(b)     = *reinterpret_cast<const float4*>(&Bs[kk][tx * 8]);
            *reinterpret_cast<float4*>(b + 4) = *reinterpret_cast<const float4*>(&Bs[kk][tx * 8 + 4]);
            #pragma unroll
            for (int i = 0; i < 8; i++)
                #pragma unroll
                for (int j = 0; j < 8; j++)
                    c[i][j] += a[i] * b[j];
        }
    }
}

// ---------------------------------------------------------------------------
// NN tile GEMM: C[128,128] += A(rows m, K contiguous) . B(rows k, N contiguous)
// B pointer is pre-offset to column n0.
// ---------------------------------------------------------------------------
__device__ __forceinline__ void gemm_tile_nn(
    const float* __restrict__ A, int lda,
    const float* __restrict__ B, int ldb,
    int Kdim, float c[8][8])
{
    __shared__ float As[BK][PAD];
    __shared__ float Bs[BK][PAD];
    const int tid  = threadIdx.x;
    const int row  = tid >> 1;
    const int vec  = (tid & 1) * 4;
    const int brow = tid >> 5;          // 0..7
    const int bcol = (tid & 31) * 4;    // 0..124
    const int tx   = tid & 15;
    const int ty   = tid >> 4;

    for (int k0 = 0; k0 < Kdim; k0 += BK) {
        float4 av = *reinterpret_cast<const float4*>(A + (size_t)row * lda + k0 + vec);
        float4 bv = *reinterpret_cast<const float4*>(B + (size_t)(k0 + brow) * ldb + bcol);
        __syncthreads();
        As[vec + 0][row] = av.x; As[vec + 1][row] = av.y;
        As[vec + 2][row] = av.z; As[vec + 3][row] = av.w;
        *reinterpret_cast<float4*>(&Bs[brow][bcol]) = bv;
        __syncthreads();
        #pragma unroll
        for (int kk = 0; kk < BK; kk++) {
            float a[8], b[8];
            *reinterpret_cast<float4*>(a)     = *reinterpret_cast<const float4*>(&As[kk][ty * 8]);
            *reinterpret_cast<float4*>(a + 4) = *reinterpret_cast<const float4*>(&As[kk][ty * 8 + 4]);
            *reinterpret_cast<float4*>(b)     = *reinterpret_cast<const float4*>(&Bs[kk][tx * 8]);
            *reinterpret_cast<float4*>(b + 4) = *reinterpret_cast<const float4*>(&Bs[kk][tx * 8 + 4]);
            #pragma unroll
            for (int i = 0; i < 8; i++)
                #pragma unroll
                for (int j = 0; j < 8; j++)
                    c[i][j] += a[i] * b[j];
        }
    }
}

// ---------------------------------------------------------------------------
// Kernel 1: QKV projections. grid.z selects W/output. Q gets 1/sqrt(d) folded in.
// ---------------------------------------------------------------------------
__global__ void __launch_bounds__(256) qkv_kernel(
    const float* __restrict__ X, const float* __restrict__ Wq,
    const float* __restrict__ Wk, const float* __restrict__ Wv)
{
    const float* W;
    float* C;
    float scale = 1.0f;
    if (blockIdx.z == 0)      { W = Wq; C = g_Q; scale = rsqrtf((float)DM); }
    else if (blockIdx.z == 1) { W = Wk; C = g_K; }
    else                      { W = Wv; C = g_V; }

    const int m0 = blockIdx.y * BM;
    const int n0 = blockIdx.x * BN;
    float c[8][8] = {};
    gemm_tile_nt(X + (size_t)m0 * DM, DM, W + (size_t)n0 * DM, DM, DM, c);

    const int tx = threadIdx.x & 15, ty = threadIdx.x >> 4;
    #pragma unroll
    for (int i = 0; i < 8; i++) {
        const size_t rbase = (size_t)(m0 + ty * 8 + i) * DM + n0 + tx * 8;
        #pragma unroll
        for (int j = 0; j < 8; j++)
            C[rbase + j] = c[i][j] * scale;
    }
}

// ---------------------------------------------------------------------------
// Kernel 2: S = Q.K^T with causal mask; blocks fully above diagonal skipped.
// ---------------------------------------------------------------------------
__global__ void __launch_bounds__(256) scores_kernel()
{
    const int b  = blockIdx.z;
    const int m0 = blockIdx.y * BM;
    const int n0 = blockIdx.x * BN;
    if (n0 > m0 + BM - 1) return;   // entirely above diagonal

    const float* Q  = g_Q + (size_t)b * SEQL * DM;
    const float* Kp = g_K + (size_t)b * SEQL * DM;
    float c[8][8] = {};
    gemm_tile_nt(Q + (size_t)m0 * DM, DM, Kp + (size_t)n0 * DM, DM, DM, c);

    float* S = g_S + (size_t)b * SEQL * SEQL;
    const int tx = threadIdx.x & 15, ty = threadIdx.x >> 4;
    const float NEGINF = __int_as_float(0xff800000);
    #pragma unroll
    for (int i = 0; i < 8; i++) {
        const int r = m0 + ty * 8 + i;
        #pragma unroll
        for (int j = 0; j < 8; j++) {
            const int cc = n0 + tx * 8 + j;
            S[(size_t)r * SEQL + cc] = (cc > r) ? NEGINF : c[i][j];
        }
    }
}

// ---------------------------------------------------------------------------
// Kernel 3: row softmax (in place) + zero-fill tail up to end of row-block,
// so the output GEMM can bound its k-loop at m0+BM.
// ---------------------------------------------------------------------------
__global__ void __launch_bounds__(256) softmax_kernel()
{
    const int rowg = blockIdx.x;
    const int b = rowg / SEQL;
    const int r = rowg % SEQL;
    float* S = g_S + (size_t)b * SEQL * SEQL + (size_t)r * SEQL;
    const int len = r + 1;
    const int t = threadIdx.x;
    __shared__ float red[256];

    float m = -3.4e38f;
    for (int j = t; j < len; j += 256) m = fmaxf(m, S[j]);
    red[t] = m; __syncthreads();
    for (int s = 128; s > 0; s >>= 1) {
        if (t < s) red[t] = fmaxf(red[t], red[t + s]);
        __syncthreads();
    }
    m = red[0]; __syncthreads();

    float sum = 0.0f;
    for (int j = t; j < len; j += 256) {
        float e = __expf(S[j] - m);
        S[j] = e;
        sum += e;
    }
    red[t] = sum; __syncthreads();
    for (int s = 128; s > 0; s >>= 1) {
        if (t < s) red[t] += red[t + s];
        __syncthreads();
    }
    const float inv = 1.0f / red[0];

    for (int j = t; j < len; j += 256) S[j] *= inv;

    const int blockend = ((r / BM) + 1) * BM;   // <= SEQL
    for (int j = len + t; j < blockend; j += 256) S[j] = 0.0f;
}

// ---------------------------------------------------------------------------
// Kernel 4: O = P.V, k-loop bounded at m0+BM (causal sparsity).
// ---------------------------------------------------------------------------
__global__ void __launch_bounds__(256) out_kernel(float* __restrict__ out)
{
    const int b  = blockIdx.z;
    const int m0 = blockIdx.y * BM;
    const int n0 = blockIdx.x * BN;
    const float* P = g_S + (size_t)b * SEQL * SEQL;
    const float* V = g_V + (size_t)b * SEQL * DM;
    const int kmax = m0 + BM;   // rows above m0+BM contribute zeros

    float c[8][8] = {};
    gemm_tile_nn(P + (size_t)m0 * SEQL, SEQL, V + n0, DM, kmax, c);

    const int tx = threadIdx.x & 15, ty = threadIdx.x >> 4;
    float* O = out + (size_t)b * SEQL * DM;
    #pragma unroll
    for (int i = 0; i < 8; i++) {
        const size_t rbase = (size_t)(m0 + ty * 8 + i) * DM + n0 + tx * 8;
        #pragma unroll
        for (int j = 0; j < 8; j++)
            O[rbase + j] = c[i][j];
    }
}

// ---------------------------------------------------------------------------
extern "C" void kernel_launch(void* const* d_in, const int* in_sizes, int n_in,
                              void* d_out, int out_size)
{
    const float* x  = (const float*)d_in[0];
    const float* Wq = (const float*)d_in[1];
    const float* Wk = (const float*)d_in[2];
    const float* Wv = (const float*)d_in[3];
    float* out = (float*)d_out;

    qkv_kernel<<<dim3(DM / BN, MTOT / BM, 3), 256>>>(x, Wq, Wk, Wv);
    scores_kernel<<<dim3(SEQL / BN, SEQL / BM, NB), 256>>>();
    softmax_kernel<<<MTOT, 256>>>();
    out_kernel<<<dim3(DM / BN, SEQL / BM, NB), 256>>>(out);
}

// round 3
// speedup vs baseline: 2.8404x; 2.8404x over previous
#include <cuda_runtime.h>
#include <stdint.h>

#define SEQL 2048
#define NB   4
#define DM   768
#define MTOT (NB*SEQL)

#define TM 128
#define TN 256
#define BK 16
#define SA   20     // A tile row stride (floats): [m][k], pad 4 -> conflict-free
#define SBNT 20     // B NT tile [n][k], pad 4
#define SBNN 264    // B NN tile [k][n], pad 8

__device__ float g_Q[(size_t)MTOT*DM];
__device__ float g_K[(size_t)MTOT*DM];
__device__ float g_V[(size_t)MTOT*DM];
__device__ float g_S[(size_t)NB*SEQL*SEQL];

// round fp32 -> tf32 (round-to-nearest), result stored back in a float container
static __device__ __forceinline__ float rnd32(float x){
    uint32_t u; asm("cvt.rna.tf32.f32 %0, %1;" : "=r"(u) : "f"(x));
    return __uint_as_float(u);
}

static __device__ __forceinline__ void mma8(float d[4], const uint32_t a[4], const uint32_t b[2]){
    asm volatile("mma.sync.aligned.m16n8k8.row.col.f32.tf32.tf32.f32 "
        "{%0,%1,%2,%3}, {%4,%5,%6,%7}, {%8,%9}, {%0,%1,%2,%3};"
        : "+f"(d[0]),"+f"(d[1]),"+f"(d[2]),"+f"(d[3])
        : "r"(a[0]),"r"(a[1]),"r"(a[2]),"r"(a[3]),"r"(b[0]),"r"(b[1]));
}

// ---------------------------------------------------------------------------
// C[128,256] = A[128,kT] . op(B).  BNT: B is [n][k] (NT). else B is [k][n] (NN).
// A,B pointers pre-offset to the tile origin. DOCVT: round staged data to tf32.
// ---------------------------------------------------------------------------
template<bool BNT, bool DOCVT>
static __device__ __forceinline__ void gemm_run(
    const float* __restrict__ A, int lda,
    const float* __restrict__ B, int ldb,
    int kT, float C[4][8][4])
{
    __shared__ float As[TM*SA];      // 10 KB
    __shared__ float Bs[TN*SBNT];    // 20 KB (NN uses 16*264 < this)

    const int t    = threadIdx.x;
    const int lane = t & 31;
    const int wid  = t >> 5;
    const int g    = lane >> 2, tg = lane & 3;
    const int wm   = (wid & 1) * 64, wn = (wid >> 1) * 64;

    float4 ra[2], rb[4];
    #pragma unroll
    for (int i=0;i<2;i++){ int f=t+i*256;
        ra[i] = *(const float4*)(A + (size_t)(f>>2)*lda + (f&3)*4); }
    #pragma unroll
    for (int i=0;i<4;i++){ int f=t+i*256;
        rb[i] = BNT ? *(const float4*)(B + (size_t)(f>>2)*ldb + (f&3)*4)
                    : *(const float4*)(B + (size_t)(f>>6)*ldb + (f&63)*4); }

    const int nIt = kT / BK;
    for (int it=0; it<nIt; it++){
        #pragma unroll
        for (int i=0;i<2;i++){
            int f=t+i*256; float4 v=ra[i];
            if (DOCVT){ v.x=rnd32(v.x); v.y=rnd32(v.y); v.z=rnd32(v.z); v.w=rnd32(v.w); }
            *(float4*)&As[(f>>2)*SA + (f&3)*4] = v;
        }
        #pragma unroll
        for (int i=0;i<4;i++){
            int f=t+i*256; float4 v=rb[i];
            if (DOCVT){ v.x=rnd32(v.x); v.y=rnd32(v.y); v.z=rnd32(v.z); v.w=rnd32(v.w); }
            if (BNT) *(float4*)&Bs[(f>>2)*SBNT + (f&3)*4] = v;
            else     *(float4*)&Bs[(f>>6)*SBNN + (f&63)*4] = v;
        }
        __syncthreads();
        if (it+1 < nIt){
            const int k0 = (it+1)*BK;
            #pragma unroll
            for (int i=0;i<2;i++){ int f=t+i*256;
                ra[i] = *(const float4*)(A + (size_t)(f>>2)*lda + k0 + (f&3)*4); }
            #pragma unroll
            for (int i=0;i<4;i++){ int f=t+i*256;
                rb[i] = BNT ? *(const float4*)(B + (size_t)(f>>2)*ldb + k0 + (f&3)*4)
                            : *(const float4*)(B + (size_t)(k0 + (f>>6))*ldb + (f&63)*4); }
        }
        #pragma unroll
        for (int ks=0; ks<2; ks++){
            uint32_t af[4][4];
            #pragma unroll
            for (int mt=0; mt<4; mt++){
                const float* p = &As[(wm+mt*16+g)*SA + ks*8 + tg];
                af[mt][0]=__float_as_uint(p[0]);
                af[mt][1]=__float_as_uint(p[8*SA]);
                af[mt][2]=__float_as_uint(p[4]);
                af[mt][3]=__float_as_uint(p[8*SA+4]);
            }
            uint32_t bf[8][2];
            #pragma unroll
            for (int nt=0; nt<8; nt++){
                if (BNT){
                    const float* p = &Bs[(wn+nt*8+g)*SBNT + ks*8 + tg];
                    bf[nt][0]=__float_as_uint(p[0]);
                    bf[nt][1]=__float_as_uint(p[4]);
                } else {
                    const float* p = &Bs[(ks*8+tg)*SBNN + wn + nt*8 + g];
                    bf[nt][0]=__float_as_uint(p[0]);
                    bf[nt][1]=__float_as_uint(p[4*SBNN]);
                }
            }
            #pragma unroll
            for (int mt=0; mt<4; mt++)
                #pragma unroll
                for (int nt=0; nt<8; nt++)
                    mma8(C[mt][nt], af[mt], bf[nt]);
        }
        __syncthreads();
    }
}

// D pre-offset to (m0,n0) tile origin.
template<bool DOCVT>
static __device__ __forceinline__ void epilogue(float* D, int ldd, float C[4][8][4], float scale)
{
    const int lane = threadIdx.x & 31, wid = threadIdx.x >> 5;
    const int g = lane>>2, tg = lane&3;
    const int wm = (wid&1)*64, wn = (wid>>1)*64;
    #pragma unroll
    for (int mt=0; mt<4; mt++)
        #pragma unroll
        for (int nt=0; nt<8; nt++){
            const int r0 = wm+mt*16+g, c0 = wn+nt*8+2*tg;
            float2 v0 = make_float2(C[mt][nt][0]*scale, C[mt][nt][1]*scale);
            float2 v1 = make_float2(C[mt][nt][2]*scale, C[mt][nt][3]*scale);
            if (DOCVT){ v0.x=rnd32(v0.x); v0.y=rnd32(v0.y); v1.x=rnd32(v1.x); v1.y=rnd32(v1.y); }
            *(float2*)&D[(size_t)r0*ldd + c0]     = v0;
            *(float2*)&D[(size_t)(r0+8)*ldd + c0] = v1;
        }
}

// ---------------------------------------------------------------------------
__global__ void __launch_bounds__(256,1) qkv_k(
    const float* __restrict__ x, const float* __restrict__ Wq,
    const float* __restrict__ Wk, const float* __restrict__ Wv)
{
    const int m0 = blockIdx.y*TM, n0 = blockIdx.x*TN;
    const float* W = (blockIdx.z==0) ? Wq : (blockIdx.z==1) ? Wk : Wv;
    float*       Cd = (blockIdx.z==0) ? g_Q : (blockIdx.z==1) ? g_K : g_V;
    const float scale = (blockIdx.z==0) ? rsqrtf((float)DM) : 1.0f;

    float C[4][8][4] = {};
    gemm_run<true, true>(x + (size_t)m0*DM, DM, W + (size_t)n0*DM, DM, DM, C);
    epilogue<true>(Cd + (size_t)m0*DM + n0, DM, C, scale);   // rounded for next GEMMs
}

__global__ void __launch_bounds__(256,1) scores_k()
{
    const int b = blockIdx.z, m0 = blockIdx.y*TM, n0 = blockIdx.x*TN;
    if (n0 >= m0 + TM) return;               // tile fully above diagonal
    const float* Q  = g_Q + ((size_t)b*SEQL + m0)*DM;
    const float* Kp = g_K + ((size_t)b*SEQL + n0)*DM;
    float C[4][8][4] = {};
    gemm_run<true, false>(Q, DM, Kp, DM, DM, C);
    epilogue<false>(g_S + (size_t)b*SEQL*SEQL + (size_t)m0*SEQL + n0, SEQL, C, 1.0f);
}

__global__ void __launch_bounds__(256) softmax_k()
{
    const int rowg = blockIdx.x;
    const int b = rowg / SEQL, r = rowg % SEQL;
    float* S = g_S + (size_t)b*SEQL*SEQL + (size_t)r*SEQL;
    const int len = r + 1, t = threadIdx.x;
    __shared__ float red[256];

    float m = -3.4e38f;
    for (int j = t; j < len; j += 256) m = fmaxf(m, S[j]);
    red[t] = m; __syncthreads();
    for (int s = 128; s > 0; s >>= 1) { if (t < s) red[t] = fmaxf(red[t], red[t+s]); __syncthreads(); }
    m = red[0]; __syncthreads();

    float sum = 0.0f;
    for (int j = t; j < len; j += 256) { float e = __expf(S[j]-m); S[j] = e; sum += e; }
    red[t] = sum; __syncthreads();
    for (int s = 128; s > 0; s >>= 1) { if (t < s) red[t] += red[t+s]; __syncthreads(); }
    const float inv = 1.0f / red[0];

    for (int j = t; j < len; j += 256) S[j] = rnd32(S[j] * inv);   // tf32-round P
    const int blockend = ((r / TM) + 1) * TM;
    for (int j = len + t; j < blockend; j += 256) S[j] = 0.0f;
}

__global__ void __launch_bounds__(256,1) out_k(float* __restrict__ out)
{
    const int b = blockIdx.z, m0 = blockIdx.y*TM, n0 = blockIdx.x*TN;
    const float* P = g_S + (size_t)b*SEQL*SEQL + (size_t)m0*SEQL;
    const float* V = g_V + (size_t)b*SEQL*DM + n0;
    float C[4][8][4] = {};
    gemm_run<false, false>(P, SEQL, V, DM, m0 + TM, C);   // K bounded by causality
    epilogue<false>(out + ((size_t)b*SEQL + m0)*DM + n0, DM, C, 1.0f);
}

// ---------------------------------------------------------------------------
extern "C" void kernel_launch(void* const* d_in, const int* in_sizes, int n_in,
                              void* d_out, int out_size)
{
    const float* x  = (const float*)d_in[0];
    const float* Wq = (const float*)d_in[1];
    const float* Wk = (const float*)d_in[2];
    const float* Wv = (const float*)d_in[3];
    float* out = (float*)d_out;

    qkv_k   <<<dim3(DM/TN, MTOT/TM, 3),   256>>>(x, Wq, Wk, Wv);
    scores_k<<<dim3(SEQL/TN, SEQL/TM, NB), 256>>>();
    softmax_k<<<MTOT, 256>>>();
    out_k   <<<dim3(DM/TN, SEQL/TM, NB),  256>>>(out);
}

// round 4
// speedup vs baseline: 3.1544x; 1.1105x over previous
#include <cuda_runtime.h>
#include <stdint.h>

#define SEQL 2048
#define NB   4
#define DM   768
#define MTOT (NB*SEQL)

#define TM 128
#define TN 256
#define BK 16
#define SA   20      // A stage row stride (floats)
#define SBNT 20      // B NT stage row stride
#define SBNN 264     // B NN stage row stride
#define STAGES 3
#define AS_BYTES (TM*SA*4)              // 10240
#define BS_BYTES (TN*SBNT*4)            // 20480 (>= 16*264*4)
#define STAGE_BYTES (AS_BYTES + BS_BYTES)
#define SMEM_TOTAL (STAGES*STAGE_BYTES) // 92160

__device__ float g_X[(size_t)MTOT*DM];      // tf32-rounded x
__device__ float g_W[(size_t)3*DM*DM];      // tf32-rounded Wq|Wk|Wv
__device__ float g_Q[(size_t)MTOT*DM];
__device__ float g_K[(size_t)MTOT*DM];
__device__ float g_V[(size_t)MTOT*DM];
__device__ float g_S[(size_t)NB*SEQL*SEQL];

static __device__ __forceinline__ float rnd32(float x){
    uint32_t u; asm("cvt.rna.tf32.f32 %0, %1;" : "=r"(u) : "f"(x));
    return __uint_as_float(u);
}
static __device__ __forceinline__ void cp16(uint32_t s, const void* g){
    asm volatile("cp.async.cg.shared.global [%0], [%1], 16;" :: "r"(s), "l"(g) : "memory");
}
static __device__ __forceinline__ void mma8(float d[4], const uint32_t a[4], const uint32_t b[2]){
    asm volatile("mma.sync.aligned.m16n8k8.row.col.f32.tf32.tf32.f32 "
        "{%0,%1,%2,%3}, {%4,%5,%6,%7}, {%8,%9}, {%0,%1,%2,%3};"
        : "+f"(d[0]),"+f"(d[1]),"+f"(d[2]),"+f"(d[3])
        : "r"(a[0]),"r"(a[1]),"r"(a[2]),"r"(a[3]),"r"(b[0]),"r"(b[1]));
}

// ---------------------------------------------------------------------------
// C[128,256] = A[128,kT] . op(B) with cp.async 3-stage pipeline.
// BNT: B is [n][k]; else B is [k][n]. Pointers pre-offset to tile origin.
// ---------------------------------------------------------------------------
template<bool BNT>
static __device__ __forceinline__ void gemm_run(
    const float* __restrict__ A, int lda,
    const float* __restrict__ B, int ldb,
    int kT, float C[4][8][4])
{
    extern __shared__ char smx[];
    const uint32_t sbase = (uint32_t)__cvta_generic_to_shared(smx);
    const int t = threadIdx.x, lane = t & 31, wid = t >> 5;
    const int g = lane >> 2, tg = lane & 3;
    const int wm = (wid & 1) * 64, wn = (wid >> 1) * 64;
    const int nIt = kT / BK;

    // stage-issue: k-chunk c into ring buffer (c % STAGES)
    auto issue = [&](int c){
        const int buf = c % STAGES;
        const uint32_t ab = sbase + buf*STAGE_BYTES;
        const uint32_t bb = ab + AS_BYTES;
        const int k0 = c * BK;
        #pragma unroll
        for (int i=0;i<2;i++){
            int f = t + i*256, row = f>>2, seg = f&3;
            cp16(ab + row*(SA*4) + seg*16, A + (size_t)row*lda + k0 + seg*4);
        }
        #pragma unroll
        for (int i=0;i<4;i++){
            int f = t + i*256;
            if (BNT){
                int row = f>>2, seg = f&3;
                cp16(bb + row*(SBNT*4) + seg*16, B + (size_t)row*ldb + k0 + seg*4);
            } else {
                int row = f>>6, seg = f&63;
                cp16(bb + row*(SBNN*4) + seg*16, B + (size_t)(k0+row)*ldb + seg*4);
            }
        }
        asm volatile("cp.async.commit_group;" ::: "memory");
    };

    #pragma unroll
    for (int s=0; s<STAGES-1; s++) issue(s);

    for (int it=0; it<nIt; it++){
        asm volatile("cp.async.wait_group %0;" :: "n"(STAGES-2) : "memory");
        __syncthreads();

        if (it + STAGES-1 < nIt) issue(it + STAGES-1);
        else asm volatile("cp.async.commit_group;" ::: "memory");

        const float* As = (const float*)(smx + (it%STAGES)*STAGE_BYTES);
        const float* Bs = (const float*)((const char*)As + AS_BYTES);

        #pragma unroll
        for (int ks=0; ks<2; ks++){
            uint32_t af[4][4];
            #pragma unroll
            for (int mt=0; mt<4; mt++){
                const float* p = &As[(wm+mt*16+g)*SA + ks*8 + tg];
                af[mt][0]=__float_as_uint(p[0]);
                af[mt][1]=__float_as_uint(p[8*SA]);
                af[mt][2]=__float_as_uint(p[4]);
                af[mt][3]=__float_as_uint(p[8*SA+4]);
            }
            uint32_t bf[8][2];
            #pragma unroll
            for (int nt=0; nt<8; nt++){
                if (BNT){
                    const float* p = &Bs[(wn+nt*8+g)*SBNT + ks*8 + tg];
                    bf[nt][0]=__float_as_uint(p[0]);
                    bf[nt][1]=__float_as_uint(p[4]);
                } else {
                    const float* p = &Bs[(ks*8+tg)*SBNN + wn + nt*8 + g];
                    bf[nt][0]=__float_as_uint(p[0]);
                    bf[nt][1]=__float_as_uint(p[4*SBNN]);
                }
            }
            #pragma unroll
            for (int mt=0; mt<4; mt++)
                #pragma unroll
                for (int nt=0; nt<8; nt++)
                    mma8(C[mt][nt], af[mt], bf[nt]);
        }
    }
}

template<bool DOCVT>
static __device__ __forceinline__ void epilogue(float* D, int ldd, float C[4][8][4], float scale)
{
    const int lane = threadIdx.x & 31, wid = threadIdx.x >> 5;
    const int g = lane>>2, tg = lane&3;
    const int wm = (wid&1)*64, wn = (wid>>1)*64;
    #pragma unroll
    for (int mt=0; mt<4; mt++)
        #pragma unroll
        for (int nt=0; nt<8; nt++){
            const int r0 = wm+mt*16+g, c0 = wn+nt*8+2*tg;
            float2 v0 = make_float2(C[mt][nt][0]*scale, C[mt][nt][1]*scale);
            float2 v1 = make_float2(C[mt][nt][2]*scale, C[mt][nt][3]*scale);
            if (DOCVT){ v0.x=rnd32(v0.x); v0.y=rnd32(v0.y); v1.x=rnd32(v1.x); v1.y=rnd32(v1.y); }
            *(float2*)&D[(size_t)r0*ldd + c0]     = v0;
            *(float2*)&D[(size_t)(r0+8)*ldd + c0] = v1;
        }
}

// ---------------------------------------------------------------------------
__global__ void __launch_bounds__(256) round_k(
    const float* __restrict__ src, float* __restrict__ dst, int n4)
{
    int i = blockIdx.x*256 + threadIdx.x;
    if (i < n4){
        float4 v = ((const float4*)src)[i];
        v.x=rnd32(v.x); v.y=rnd32(v.y); v.z=rnd32(v.z); v.w=rnd32(v.w);
        ((float4*)dst)[i] = v;
    }
}

__global__ void __launch_bounds__(256,1) qkv_k()
{
    const int m0 = blockIdx.y*TM, n0 = blockIdx.x*TN;
    const float* W = g_W + (size_t)blockIdx.z*DM*DM;
    float*      Cd = (blockIdx.z==0) ? g_Q : (blockIdx.z==1) ? g_K : g_V;
    const float scale = (blockIdx.z==0) ? rsqrtf((float)DM) : 1.0f;

    float C[4][8][4] = {};
    gemm_run<true>(g_X + (size_t)m0*DM, DM, W + (size_t)n0*DM, DM, DM, C);
    epilogue<true>(Cd + (size_t)m0*DM + n0, DM, C, scale);
}

__global__ void __launch_bounds__(256,1) scores_k()
{
    const int b = blockIdx.z, m0 = (gridDim.y-1-blockIdx.y)*TM, n0 = blockIdx.x*TN;
    if (n0 >= m0 + TM) return;
    const float* Q  = g_Q + ((size_t)b*SEQL + m0)*DM;
    const float* Kp = g_K + ((size_t)b*SEQL + n0)*DM;
    float C[4][8][4] = {};
    gemm_run<true>(Q, DM, Kp, DM, DM, C);
    epilogue<false>(g_S + (size_t)b*SEQL*SEQL + (size_t)m0*SEQL + n0, SEQL, C, 1.0f);
}

// two-pass softmax: online (max,sum) read pass, then fused normalize+round write
__global__ void __launch_bounds__(256) softmax_k()
{
    const int rowg = blockIdx.x;
    const int b = rowg / SEQL, r = rowg % SEQL;
    float* S = g_S + (size_t)b*SEQL*SEQL + (size_t)r*SEQL;
    const int len = r + 1, t = threadIdx.x;
    __shared__ float rm[256], rs[256];

    float m = -3.4e38f, s = 0.0f;
    for (int j = t; j < len; j += 256){
        float v = S[j];
        float nm = fmaxf(m, v);
        s = s*__expf(m-nm) + __expf(v-nm);
        m = nm;
    }
    rm[t] = m; rs[t] = s; __syncthreads();
    for (int st = 128; st > 0; st >>= 1){
        if (t < st){
            float m2 = rm[t+st], s2 = rs[t+st];
            float nm = fmaxf(rm[t], m2);
            rs[t] = rs[t]*__expf(rm[t]-nm) + s2*__expf(m2-nm);
            rm[t] = nm;
        }
        __syncthreads();
    }
    m = rm[0];
    const float inv = 1.0f / rs[0];

    for (int j = t; j < len; j += 256) S[j] = rnd32(__expf(S[j]-m) * inv);
    const int blockend = ((r / TM) + 1) * TM;
    for (int j = len + t; j < blockend; j += 256) S[j] = 0.0f;
}

__global__ void __launch_bounds__(256,1) out_k(float* __restrict__ out)
{
    const int b = blockIdx.z, m0 = (gridDim.y-1-blockIdx.y)*TM, n0 = blockIdx.x*TN;
    const float* P = g_S + (size_t)b*SEQL*SEQL + (size_t)m0*SEQL;
    const float* V = g_V + (size_t)b*SEQL*DM + n0;
    float C[4][8][4] = {};
    gemm_run<false>(P, SEQL, V, DM, m0 + TM, C);
    epilogue<false>(out + ((size_t)b*SEQL + m0)*DM + n0, DM, C, 1.0f);
}

// ---------------------------------------------------------------------------
extern "C" void kernel_launch(void* const* d_in, const int* in_sizes, int n_in,
                              void* d_out, int out_size)
{
    const float* x  = (const float*)d_in[0];
    const float* Wq = (const float*)d_in[1];
    const float* Wk = (const float*)d_in[2];
    const float* Wv = (const float*)d_in[3];
    float* out = (float*)d_out;

    static int inited = 0;
    if (!inited){
        cudaFuncSetAttribute(qkv_k,    cudaFuncAttributeMaxDynamicSharedMemorySize, SMEM_TOTAL);
        cudaFuncSetAttribute(scores_k, cudaFuncAttributeMaxDynamicSharedMemorySize, SMEM_TOTAL);
        cudaFuncSetAttribute(out_k,    cudaFuncAttributeMaxDynamicSharedMemorySize, SMEM_TOTAL);
        inited = 1;
    }

    float* gX; cudaGetSymbolAddress((void**)&gX, g_X);
    float* gW; cudaGetSymbolAddress((void**)&gW, g_W);

    const int nx4 = MTOT*DM/4, nw4 = DM*DM/4;
    round_k<<<(nx4+255)/256, 256>>>(x,  gX,           nx4);
    round_k<<<(nw4+255)/256, 256>>>(Wq, gW,           nw4);
    round_k<<<(nw4+255)/256, 256>>>(Wk, gW + (size_t)DM*DM,   nw4);
    round_k<<<(nw4+255)/256, 256>>>(Wv, gW + (size_t)2*DM*DM, nw4);

    qkv_k   <<<dim3(DM/TN, MTOT/TM, 3),   256, SMEM_TOTAL>>>();
    scores_k<<<dim3(SEQL/TN, SEQL/TM, NB), 256, SMEM_TOTAL>>>();
    softmax_k<<<MTOT, 256>>>();
    out_k   <<<dim3(DM/TN, SEQL/TM, NB),  256, SMEM_TOTAL>>>(out);
}

// round 5
// speedup vs baseline: 5.3515x; 1.6965x over previous
#include <cuda_runtime.h>
#include <cuda_fp16.h>
#include <stdint.h>

#define SEQL 2048
#define NB   4
#define DM   768
#define MTOT (NB*SEQL)

#define TM 128
#define TN 256
#define BK 32
// half-element row strides (padded): A/P [m][k]: 32+8=40 halves (80 B, 5 chunks)
// B NT [n][k]: 40 halves; B NN [k][n]: 256+8=264 halves (528 B, 33 chunks)
#define SAH   40
#define SBNTH 40
#define SBNNH 264
#define STAGES 3
#define AS_BYTES (TM*SAH*2)               // 10240
#define BS_BYTES (TN*SBNTH*2)             // 20480 (>= 32*264*2 = 16896)
#define STAGE_BYTES (AS_BYTES + BS_BYTES) // 30720
#define SMEM_TOTAL (STAGES*STAGE_BYTES)   // 92160

__device__ __half g_X[(size_t)MTOT*DM];
__device__ __half g_W[(size_t)3*DM*DM];
__device__ __half g_Q[(size_t)MTOT*DM];
__device__ __half g_K[(size_t)MTOT*DM];
__device__ __half g_V[(size_t)MTOT*DM];
__device__ float  g_S[(size_t)NB*SEQL*SEQL];
__device__ __half g_P[(size_t)NB*SEQL*SEQL];

static __device__ __forceinline__ void cp16(uint32_t s, const void* g){
    asm volatile("cp.async.cg.shared.global [%0], [%1], 16;" :: "r"(s), "l"(g) : "memory");
}
static __device__ __forceinline__ void ldsm4(uint32_t r[4], uint32_t a){
    asm volatile("ldmatrix.sync.aligned.m8n8.x4.shared.b16 {%0,%1,%2,%3}, [%4];"
        : "=r"(r[0]),"=r"(r[1]),"=r"(r[2]),"=r"(r[3]) : "r"(a));
}
static __device__ __forceinline__ void ldsm4t(uint32_t r[4], uint32_t a){
    asm volatile("ldmatrix.sync.aligned.m8n8.x4.trans.shared.b16 {%0,%1,%2,%3}, [%4];"
        : "=r"(r[0]),"=r"(r[1]),"=r"(r[2]),"=r"(r[3]) : "r"(a));
}
static __device__ __forceinline__ void mma16(float d[4], const uint32_t a[4], uint32_t b0, uint32_t b1){
    asm volatile("mma.sync.aligned.m16n8k16.row.col.f32.f16.f16.f32 "
        "{%0,%1,%2,%3}, {%4,%5,%6,%7}, {%8,%9}, {%0,%1,%2,%3};"
        : "+f"(d[0]),"+f"(d[1]),"+f"(d[2]),"+f"(d[3])
        : "r"(a[0]),"r"(a[1]),"r"(a[2]),"r"(a[3]),"r"(b0),"r"(b1));
}

// ---------------------------------------------------------------------------
// C[128,256] = A[128,kT] . op(B), fp16 operands, fp32 accum, 3-stage cp.async.
// BNT: B stored [n][k]; else B stored [k][n] (loaded via ldmatrix.trans).
// ---------------------------------------------------------------------------
template<bool BNT>
static __device__ __forceinline__ void gemm_run(
    const __half* __restrict__ A, int lda,
    const __half* __restrict__ B, int ldb,
    int kT, float C[4][8][4])
{
    extern __shared__ char smx[];
    const uint32_t sbase = (uint32_t)__cvta_generic_to_shared(smx);
    const int t = threadIdx.x, lane = t & 31, wid = t >> 5;
    const int wm = (wid & 1) * 64, wn = (wid >> 1) * 64;
    const int lrow = (lane & 7) + ((lane >> 3) & 1) * 8;  // ldmatrix row-in-16
    const int loct = lane >> 4;                            // ldmatrix 8-octet sel
    const int nIt = kT / BK;

    auto issue = [&](int c){
        const int buf = c % STAGES;
        const uint32_t ab = sbase + buf*STAGE_BYTES;
        const uint32_t bb = ab + AS_BYTES;
        const int k0 = c * BK;
        #pragma unroll
        for (int i=0;i<2;i++){                        // A: 128 rows x 64 B
            int f = t + i*256, row = f>>2, seg = f&3;
            cp16(ab + row*(SAH*2) + seg*16, A + (size_t)row*lda + k0 + seg*8);
        }
        #pragma unroll
        for (int i=0;i<4;i++){
            int f = t + i*256;
            if (BNT){                                 // 256 rows x 64 B
                int row = f>>2, seg = f&3;
                cp16(bb + row*(SBNTH*2) + seg*16, B + (size_t)row*ldb + k0 + seg*8);
            } else {                                  // 32 rows x 512 B
                int row = f>>5, seg = f&31;
                cp16(bb + row*(SBNNH*2) + seg*16, B + (size_t)(k0+row)*ldb + seg*8);
            }
        }
        asm volatile("cp.async.commit_group;" ::: "memory");
    };

    #pragma unroll
    for (int s=0; s<STAGES-1; s++) issue(s);

    for (int it=0; it<nIt; it++){
        asm volatile("cp.async.wait_group %0;" :: "n"(STAGES-2) : "memory");
        __syncthreads();
        if (it + STAGES-1 < nIt) issue(it + STAGES-1);
        else asm volatile("cp.async.commit_group;" ::: "memory");

        const uint32_t as = sbase + (it%STAGES)*STAGE_BYTES;
        const uint32_t bs = as + AS_BYTES;

        #pragma unroll
        for (int ks=0; ks<2; ks++){
            uint32_t af[4][4];
            #pragma unroll
            for (int mt=0; mt<4; mt++)
                ldsm4(af[mt], as + (wm + mt*16 + lrow)*(SAH*2) + (ks*16 + loct*8)*2);
            uint32_t bf[4][4];
            #pragma unroll
            for (int n2=0; n2<4; n2++){
                if (BNT)   // regs: [b0_even, b0_odd, b1_even, b1_odd]
                    ldsm4(bf[n2], bs + (wn + n2*16 + lrow)*(SBNTH*2) + (ks*16 + loct*8)*2);
                else       // regs: [b0_even, b1_even, b0_odd, b1_odd]
                    ldsm4t(bf[n2], bs + (ks*16 + lrow)*(SBNNH*2) + (wn + n2*16 + loct*8)*2);
            }
            #pragma unroll
            for (int mt=0; mt<4; mt++)
                #pragma unroll
                for (int nt=0; nt<8; nt++){
                    const int n2 = nt>>1, od = nt&1;
                    uint32_t b0 = BNT ? bf[n2][od]   : bf[n2][od*2];
                    uint32_t b1 = BNT ? bf[n2][2+od] : bf[n2][od*2+1];
                    mma16(C[mt][nt], af[mt], b0, b1);
                }
        }
    }
}

// fp16 epilogue (Q/K/V outputs)
static __device__ __forceinline__ void epilogue_h(__half* D, int ldd, float C[4][8][4], float scale)
{
    const int lane = threadIdx.x & 31, wid = threadIdx.x >> 5;
    const int g = lane>>2, tg = lane&3;
    const int wm = (wid&1)*64, wn = (wid>>1)*64;
    #pragma unroll
    for (int mt=0; mt<4; mt++)
        #pragma unroll
        for (int nt=0; nt<8; nt++){
            const int r0 = wm+mt*16+g, c0 = wn+nt*8+2*tg;
            __half2 v0 = __floats2half2_rn(C[mt][nt][0]*scale, C[mt][nt][1]*scale);
            __half2 v1 = __floats2half2_rn(C[mt][nt][2]*scale, C[mt][nt][3]*scale);
            *(__half2*)&D[(size_t)r0*ldd + c0]     = v0;
            *(__half2*)&D[(size_t)(r0+8)*ldd + c0] = v1;
        }
}
// fp32 epilogue (S, out)
static __device__ __forceinline__ void epilogue_f(float* D, int ldd, float C[4][8][4])
{
    const int lane = threadIdx.x & 31, wid = threadIdx.x >> 5;
    const int g = lane>>2, tg = lane&3;
    const int wm = (wid&1)*64, wn = (wid>>1)*64;
    #pragma unroll
    for (int mt=0; mt<4; mt++)
        #pragma unroll
        for (int nt=0; nt<8; nt++){
            const int r0 = wm+mt*16+g, c0 = wn+nt*8+2*tg;
            *(float2*)&D[(size_t)r0*ldd + c0]     = make_float2(C[mt][nt][0], C[mt][nt][1]);
            *(float2*)&D[(size_t)(r0+8)*ldd + c0] = make_float2(C[mt][nt][2], C[mt][nt][3]);
        }
}

// ---------------------------------------------------------------------------
__global__ void __launch_bounds__(256) cvt_k(
    const float4* __restrict__ src, __half* __restrict__ dst, int n4)
{
    int i = blockIdx.x*256 + threadIdx.x;
    if (i < n4){
        float4 v = src[i];
        __half2 h0 = __floats2half2_rn(v.x, v.y);
        __half2 h1 = __floats2half2_rn(v.z, v.w);
        ((uint2*)dst)[i] = make_uint2(*(uint32_t*)&h0, *(uint32_t*)&h1);
    }
}

__global__ void __launch_bounds__(256,1) qkv_k()
{
    const int m0 = blockIdx.y*TM, n0 = blockIdx.x*TN;
    const __half* W = g_W + (size_t)blockIdx.z*DM*DM;
    __half*      Cd = (blockIdx.z==0) ? g_Q : (blockIdx.z==1) ? g_K : g_V;
    const float scale = (blockIdx.z==0) ? rsqrtf((float)DM) : 1.0f;

    float C[4][8][4] = {};
    gemm_run<true>(g_X + (size_t)m0*DM, DM, W + (size_t)n0*DM, DM, DM, C);
    epilogue_h(Cd + (size_t)m0*DM + n0, DM, C, scale);
}

__global__ void __launch_bounds__(256,1) scores_k()
{
    const int b = blockIdx.z, m0 = (gridDim.y-1-blockIdx.y)*TM, n0 = blockIdx.x*TN;
    if (n0 >= m0 + TM) return;
    float C[4][8][4] = {};
    gemm_run<true>(g_Q + ((size_t)b*SEQL + m0)*DM, DM,
                   g_K + ((size_t)b*SEQL + n0)*DM, DM, DM, C);
    epilogue_f(g_S + (size_t)b*SEQL*SEQL + (size_t)m0*SEQL + n0, SEQL, C);
}

// softmax: read fp32 S (cols <= row only), write fp16 P + zero tail to block end
__global__ void __launch_bounds__(256) softmax_k()
{
    const int rowg = blockIdx.x;
    const int b = rowg / SEQL, r = rowg % SEQL;
    const float* S = g_S + (size_t)b*SEQL*SEQL + (size_t)r*SEQL;
    __half*     P  = g_P + (size_t)b*SEQL*SEQL + (size_t)r*SEQL;
    const int len = r + 1, t = threadIdx.x;
    __shared__ float rm[256], rs[256];

    float m = -3.4e38f, s = 0.0f;
    for (int j = t; j < len; j += 256){
        float v = S[j];
        float nm = fmaxf(m, v);
        s = s*__expf(m-nm) + __expf(v-nm);
        m = nm;
    }
    rm[t] = m; rs[t] = s; __syncthreads();
    for (int st = 128; st > 0; st >>= 1){
        if (t < st){
            float m2 = rm[t+st], s2 = rs[t+st];
            float nm = fmaxf(rm[t], m2);
            rs[t] = rs[t]*__expf(rm[t]-nm) + s2*__expf(m2-nm);
            rm[t] = nm;
        }
        __syncthreads();
    }
    m = rm[0];
    const float inv = 1.0f / rs[0];

    for (int j = t; j < len; j += 256) P[j] = __float2half_rn(__expf(S[j]-m) * inv);
    const int blockend = ((r / TM) + 1) * TM;
    for (int j = len + t; j < blockend; j += 256) P[j] = __float2half_rn(0.0f);
}

__global__ void __launch_bounds__(256,1) out_k(float* __restrict__ out)
{
    const int b = blockIdx.z, m0 = (gridDim.y-1-blockIdx.y)*TM, n0 = blockIdx.x*TN;
    float C[4][8][4] = {};
    gemm_run<false>(g_P + (size_t)b*SEQL*SEQL + (size_t)m0*SEQL, SEQL,
                    g_V + (size_t)b*SEQL*DM + n0, DM, m0 + TM, C);
    epilogue_f(out + ((size_t)b*SEQL + m0)*DM + n0, DM, C);
}

// ---------------------------------------------------------------------------
extern "C" void kernel_launch(void* const* d_in, const int* in_sizes, int n_in,
                              void* d_out, int out_size)
{
    const float* x  = (const float*)d_in[0];
    const float* Wq = (const float*)d_in[1];
    const float* Wk = (const float*)d_in[2];
    const float* Wv = (const float*)d_in[3];
    float* out = (float*)d_out;

    static int inited = 0;
    if (!inited){
        cudaFuncSetAttribute(qkv_k,    cudaFuncAttributeMaxDynamicSharedMemorySize, SMEM_TOTAL);
        cudaFuncSetAttribute(scores_k, cudaFuncAttributeMaxDynamicSharedMemorySize, SMEM_TOTAL);
        cudaFuncSetAttribute(out_k,    cudaFuncAttributeMaxDynamicSharedMemorySize, SMEM_TOTAL);
        inited = 1;
    }

    __half* gX; cudaGetSymbolAddress((void**)&gX, g_X);
    __half* gW; cudaGetSymbolAddress((void**)&gW, g_W);

    const int nx4 = MTOT*DM/4, nw4 = DM*DM/4;
    cvt_k<<<(nx4+255)/256, 256>>>((const float4*)x,  gX,                     nx4);
    cvt_k<<<(nw4+255)/256, 256>>>((const float4*)Wq, gW,                     nw4);
    cvt_k<<<(nw4+255)/256, 256>>>((const float4*)Wk, gW + (size_t)DM*DM,     nw4);
    cvt_k<<<(nw4+255)/256, 256>>>((const float4*)Wv, gW + (size_t)2*DM*DM,   nw4);

    qkv_k   <<<dim3(DM/TN, MTOT/TM, 3),    256, SMEM_TOTAL>>>();
    scores_k<<<dim3(SEQL/TN, SEQL/TM, NB), 256, SMEM_TOTAL>>>();
    softmax_k<<<MTOT, 256>>>();
    out_k   <<<dim3(DM/TN, SEQL/TM, NB),   256, SMEM_TOTAL>>>(out);
}

// round 6
// speedup vs baseline: 5.9545x; 1.1127x over previous
#include <cuda_runtime.h>
#include <cuda_fp16.h>
#include <stdint.h>

#define SEQL 2048
#define NB   4
#define DM   768
#define MTOT (NB*SEQL)

#define TM 128
#define TN 128
#define BK 32
#define NTHR 128
// half strides: A/P [m][k] & B NT [n][k]: 32+8=40 halves (80B); B NN [k][n]: 128+8=136 halves (272B)
#define SAH   40
#define SBNTH 40
#define SBNNH 136
#define STAGES 4
#define AS_BYTES (TM*SAH*2)               // 10240
#define BS_BYTES (TN*SBNTH*2)             // 10240 (>= 32*136*2 = 8704)
#define STAGE_BYTES (AS_BYTES + BS_BYTES) // 20480
#define SMEM_TOTAL (STAGES*STAGE_BYTES)   // 81920

__device__ __half g_X[(size_t)MTOT*DM];
__device__ __half g_W[(size_t)3*DM*DM];
__device__ __half g_Q[(size_t)MTOT*DM];
__device__ __half g_K[(size_t)MTOT*DM];
__device__ __half g_V[(size_t)MTOT*DM];
__device__ float  g_S[(size_t)NB*SEQL*SEQL];
__device__ __half g_P[(size_t)NB*SEQL*SEQL];

static __device__ __forceinline__ void cp16(uint32_t s, const void* g){
    asm volatile("cp.async.cg.shared.global [%0], [%1], 16;" :: "r"(s), "l"(g) : "memory");
}
static __device__ __forceinline__ void ldsm4(uint32_t r[4], uint32_t a){
    asm volatile("ldmatrix.sync.aligned.m8n8.x4.shared.b16 {%0,%1,%2,%3}, [%4];"
        : "=r"(r[0]),"=r"(r[1]),"=r"(r[2]),"=r"(r[3]) : "r"(a));
}
static __device__ __forceinline__ void ldsm4t(uint32_t r[4], uint32_t a){
    asm volatile("ldmatrix.sync.aligned.m8n8.x4.trans.shared.b16 {%0,%1,%2,%3}, [%4];"
        : "=r"(r[0]),"=r"(r[1]),"=r"(r[2]),"=r"(r[3]) : "r"(a));
}
static __device__ __forceinline__ void mma16(float d[4], const uint32_t a[4], uint32_t b0, uint32_t b1){
    asm volatile("mma.sync.aligned.m16n8k16.row.col.f32.f16.f16.f32 "
        "{%0,%1,%2,%3}, {%4,%5,%6,%7}, {%8,%9}, {%0,%1,%2,%3};"
        : "+f"(d[0]),"+f"(d[1]),"+f"(d[2]),"+f"(d[3])
        : "r"(a[0]),"r"(a[1]),"r"(a[2]),"r"(a[3]),"r"(b0),"r"(b1));
}

// ---------------------------------------------------------------------------
// C[128,128] = A[128,kT] . op(B), fp16 in, fp32 accum, 4-stage cp.async ring.
// BNT: B stored [n][k]; else [k][n] via ldmatrix.trans. 128 threads (4 warps).
// ---------------------------------------------------------------------------
template<bool BNT>
static __device__ __forceinline__ void gemm_run(
    const __half* __restrict__ A, int lda,
    const __half* __restrict__ B, int ldb,
    int kT, float C[4][8][4])
{
    extern __shared__ char smx[];
    const uint32_t sbase = (uint32_t)__cvta_generic_to_shared(smx);
    const int t = threadIdx.x, lane = t & 31, wid = t >> 5;
    const int wm = (wid & 1) * 64, wn = (wid >> 1) * 64;
    const int lrow = (lane & 7) + ((lane >> 3) & 1) * 8;
    const int loct = lane >> 4;
    const int nIt = kT / BK;

    auto issue = [&](int c){
        const int buf = c & (STAGES-1);
        const uint32_t ab = sbase + buf*STAGE_BYTES;
        const uint32_t bb = ab + AS_BYTES;
        const int k0 = c * BK;
        #pragma unroll
        for (int i=0;i<4;i++){                        // A: 128 rows x 64B
            int f = t + i*NTHR, row = f>>2, seg = f&3;
            cp16(ab + row*(SAH*2) + seg*16, A + (size_t)row*lda + k0 + seg*8);
        }
        #pragma unroll
        for (int i=0;i<4;i++){
            int f = t + i*NTHR;
            if (BNT){                                 // 128 rows x 64B
                int row = f>>2, seg = f&3;
                cp16(bb + row*(SBNTH*2) + seg*16, B + (size_t)row*ldb + k0 + seg*8);
            } else {                                  // 32 rows x 256B
                int row = f>>4, seg = f&15;
                cp16(bb + row*(SBNNH*2) + seg*16, B + (size_t)(k0+row)*ldb + seg*8);
            }
        }
        asm volatile("cp.async.commit_group;" ::: "memory");
    };

    #pragma unroll
    for (int s=0; s<STAGES-1; s++) issue(s);

    for (int it=0; it<nIt; it++){
        asm volatile("cp.async.wait_group %0;" :: "n"(STAGES-2) : "memory");
        __syncthreads();
        if (it + STAGES-1 < nIt) issue(it + STAGES-1);
        else asm volatile("cp.async.commit_group;" ::: "memory");

        const uint32_t as = sbase + (it & (STAGES-1))*STAGE_BYTES;
        const uint32_t bs = as + AS_BYTES;

        #pragma unroll
        for (int ks=0; ks<2; ks++){
            uint32_t af[4][4];
            #pragma unroll
            for (int mt=0; mt<4; mt++)
                ldsm4(af[mt], as + (wm + mt*16 + lrow)*(SAH*2) + (ks*16 + loct*8)*2);
            uint32_t bf[4][4];
            #pragma unroll
            for (int n2=0; n2<4; n2++){
                if (BNT)
                    ldsm4(bf[n2], bs + (wn + n2*16 + lrow)*(SBNTH*2) + (ks*16 + loct*8)*2);
                else
                    ldsm4t(bf[n2], bs + (ks*16 + lrow)*(SBNNH*2) + (wn + n2*16 + loct*8)*2);
            }
            #pragma unroll
            for (int mt=0; mt<4; mt++)
                #pragma unroll
                for (int nt=0; nt<8; nt++){
                    const int n2 = nt>>1, od = nt&1;
                    uint32_t b0 = BNT ? bf[n2][od]   : bf[n2][od*2];
                    uint32_t b1 = BNT ? bf[n2][2+od] : bf[n2][od*2+1];
                    mma16(C[mt][nt], af[mt], b0, b1);
                }
        }
    }
}

static __device__ __forceinline__ void epilogue_h(__half* D, int ldd, float C[4][8][4], float scale)
{
    const int lane = threadIdx.x & 31, wid = threadIdx.x >> 5;
    const int g = lane>>2, tg = lane&3;
    const int wm = (wid&1)*64, wn = (wid>>1)*64;
    #pragma unroll
    for (int mt=0; mt<4; mt++)
        #pragma unroll
        for (int nt=0; nt<8; nt++){
            const int r0 = wm+mt*16+g, c0 = wn+nt*8+2*tg;
            __half2 v0 = __floats2half2_rn(C[mt][nt][0]*scale, C[mt][nt][1]*scale);
            __half2 v1 = __floats2half2_rn(C[mt][nt][2]*scale, C[mt][nt][3]*scale);
            *(__half2*)&D[(size_t)r0*ldd + c0]     = v0;
            *(__half2*)&D[(size_t)(r0+8)*ldd + c0] = v1;
        }
}
static __device__ __forceinline__ void epilogue_f(float* D, int ldd, float C[4][8][4])
{
    const int lane = threadIdx.x & 31, wid = threadIdx.x >> 5;
    const int g = lane>>2, tg = lane&3;
    const int wm = (wid&1)*64, wn = (wid>>1)*64;
    #pragma unroll
    for (int mt=0; mt<4; mt++)
        #pragma unroll
        for (int nt=0; nt<8; nt++){
            const int r0 = wm+mt*16+g, c0 = wn+nt*8+2*tg;
            *(float2*)&D[(size_t)r0*ldd + c0]     = make_float2(C[mt][nt][0], C[mt][nt][1]);
            *(float2*)&D[(size_t)(r0+8)*ldd + c0] = make_float2(C[mt][nt][2], C[mt][nt][3]);
        }
}

// ---------------------------------------------------------------------------
// single conversion kernel: x then Wq|Wk|Wv into g_X / g_W
__global__ void __launch_bounds__(256) cvt_k(
    const float4* __restrict__ x, const float4* __restrict__ Wq,
    const float4* __restrict__ Wk, const float4* __restrict__ Wv)
{
    const int nx4 = MTOT*DM/4, nw4 = DM*DM/4;
    int i = blockIdx.x*256 + threadIdx.x;
    const float4* src; __half* dst; int idx;
    if (i < nx4){ src = x; dst = g_X; idx = i; }
    else {
        int j = i - nx4;
        int w = j / nw4; idx = j - w*nw4;
        src = (w==0) ? Wq : (w==1) ? Wk : Wv;
        dst = g_W + (size_t)w*DM*DM;
    }
    float4 v = src[idx];
    __half2 h0 = __floats2half2_rn(v.x, v.y);
    __half2 h1 = __floats2half2_rn(v.z, v.w);
    ((uint2*)dst)[idx] = make_uint2(*(uint32_t*)&h0, *(uint32_t*)&h1);
}

__global__ void __launch_bounds__(NTHR,2) qkv_k()
{
    const int m0 = blockIdx.y*TM, n0 = blockIdx.x*TN;
    const __half* W = g_W + (size_t)blockIdx.z*DM*DM;
    __half*      Cd = (blockIdx.z==0) ? g_Q : (blockIdx.z==1) ? g_K : g_V;
    const float scale = (blockIdx.z==0) ? rsqrtf((float)DM) : 1.0f;

    float C[4][8][4] = {};
    gemm_run<true>(g_X + (size_t)m0*DM, DM, W + (size_t)n0*DM, DM, DM, C);
    epilogue_h(Cd + (size_t)m0*DM + n0, DM, C, scale);
}

// compact lower-triangular grid: blockIdx.x in [0,136) -> (m,n), n<=m
__global__ void __launch_bounds__(NTHR,2) scores_k()
{
    const int b = blockIdx.y;
    int i = blockIdx.x;
    int m = (int)((sqrtf(8.0f*i + 1.0f) - 1.0f) * 0.5f);
    while ((m+1)*(m+2)/2 <= i) ++m;
    while (m*(m+1)/2 > i) --m;
    const int n = i - m*(m+1)/2;
    const int m0 = m*TM, n0 = n*TN;

    float C[4][8][4] = {};
    gemm_run<true>(g_Q + ((size_t)b*SEQL + m0)*DM, DM,
                   g_K + ((size_t)b*SEQL + n0)*DM, DM, DM, C);
    epilogue_f(g_S + (size_t)b*SEQL*SEQL + (size_t)m0*SEQL + n0, SEQL, C);
}

__global__ void __launch_bounds__(256) softmax_k()
{
    const int rowg = blockIdx.x;
    const int b = rowg / SEQL, r = rowg % SEQL;
    const float* S = g_S + (size_t)b*SEQL*SEQL + (size_t)r*SEQL;
    __half*     P  = g_P + (size_t)b*SEQL*SEQL + (size_t)r*SEQL;
    const int len = r + 1, t = threadIdx.x, lane = t & 31, wrp = t >> 5;
    __shared__ float rm[8], rs[8];

    float m = -3.4e38f, s = 0.0f;
    for (int j = t; j < len; j += 256){
        float v = S[j];
        float nm = fmaxf(m, v);
        s = s*__expf(m-nm) + __expf(v-nm);
        m = nm;
    }
    #pragma unroll
    for (int o = 16; o > 0; o >>= 1){
        float m2 = __shfl_xor_sync(0xffffffffu, m, o);
        float s2 = __shfl_xor_sync(0xffffffffu, s, o);
        float nm = fmaxf(m, m2);
        s = s*__expf(m-nm) + s2*__expf(m2-nm);
        m = nm;
    }
    if (lane == 0){ rm[wrp] = m; rs[wrp] = s; }
    __syncthreads();
    if (wrp == 0){
        m = (lane < 8) ? rm[lane] : -3.4e38f;
        s = (lane < 8) ? rs[lane] : 0.0f;
        #pragma unroll
        for (int o = 4; o > 0; o >>= 1){
            float m2 = __shfl_xor_sync(0xffffffffu, m, o);
            float s2 = __shfl_xor_sync(0xffffffffu, s, o);
            float nm = fmaxf(m, m2);
            s = s*__expf(m-nm) + s2*__expf(m2-nm);
            m = nm;
        }
        if (lane == 0){ rm[0] = m; rs[0] = 1.0f / s; }
    }
    __syncthreads();
    m = rm[0];
    const float inv = rs[0];

    for (int j = t; j < len; j += 256) P[j] = __float2half_rn(__expf(S[j]-m) * inv);
    const int blockend = ((r / TM) + 1) * TM;
    for (int j = len + t; j < blockend; j += 256) P[j] = __float2half_rn(0.0f);
}

__global__ void __launch_bounds__(NTHR,2) out_k(float* __restrict__ out)
{
    const int b = blockIdx.z;
    const int m0 = (gridDim.y-1-blockIdx.y)*TM, n0 = blockIdx.x*TN;
    float C[4][8][4] = {};
    gemm_run<false>(g_P + (size_t)b*SEQL*SEQL + (size_t)m0*SEQL, SEQL,
                    g_V + (size_t)b*SEQL*DM + n0, DM, m0 + TM, C);
    epilogue_f(out + ((size_t)b*SEQL + m0)*DM + n0, DM, C);
}

// ---------------------------------------------------------------------------
extern "C" void kernel_launch(void* const* d_in, const int* in_sizes, int n_in,
                              void* d_out, int out_size)
{
    const float* x  = (const float*)d_in[0];
    const float* Wq = (const float*)d_in[1];
    const float* Wk = (const float*)d_in[2];
    const float* Wv = (const float*)d_in[3];
    float* out = (float*)d_out;

    static int inited = 0;
    if (!inited){
        cudaFuncSetAttribute(qkv_k,    cudaFuncAttributeMaxDynamicSharedMemorySize, SMEM_TOTAL);
        cudaFuncSetAttribute(scores_k, cudaFuncAttributeMaxDynamicSharedMemorySize, SMEM_TOTAL);
        cudaFuncSetAttribute(out_k,    cudaFuncAttributeMaxDynamicSharedMemorySize, SMEM_TOTAL);
        inited = 1;
    }

    const int ntot4 = (MTOT*DM + 3*DM*DM)/4;
    cvt_k<<<(ntot4+255)/256, 256>>>((const float4*)x, (const float4*)Wq,
                                    (const float4*)Wk, (const float4*)Wv);

    qkv_k   <<<dim3(DM/TN, MTOT/TM, 3),  NTHR, SMEM_TOTAL>>>();
    scores_k<<<dim3(136, NB),            NTHR, SMEM_TOTAL>>>();
    softmax_k<<<MTOT, 256>>>();
    out_k   <<<dim3(DM/TN, SEQL/TM, NB), NTHR, SMEM_TOTAL>>>(out);
}

// round 7
// speedup vs baseline: 6.0885x; 1.0225x over previous
#include <cuda_runtime.h>
#include <cuda_fp16.h>
#include <stdint.h>

#define SEQL 2048
#define NB   4
#define DM   768
#define MTOT (NB*SEQL)

#define TM 128
#define TN 128
#define BK 32
#define NTHR 128
#define SAH   40
#define SBNTH 40
#define SBNNH 136
#define STAGES 4
#define AS_BYTES (TM*SAH*2)               // 10240
#define BS_BYTES (TN*SBNTH*2)             // 10240 (>= 32*136*2)
#define STAGE_BYTES (AS_BYTES + BS_BYTES) // 20480
#define SMEM_TOTAL (STAGES*STAGE_BYTES)   // 81920

__device__ __half g_X[(size_t)MTOT*DM];
__device__ __half g_W[(size_t)3*DM*DM];
__device__ __half g_Q[(size_t)MTOT*DM];
__device__ __half g_K[(size_t)MTOT*DM];
__device__ __half g_V[(size_t)MTOT*DM];
__device__ float  g_S[(size_t)NB*SEQL*SEQL];
__device__ __half g_P[(size_t)NB*SEQL*SEQL];
__device__ float  g_Inv[MTOT];

static __device__ __forceinline__ void cp16(uint32_t s, const void* g){
    asm volatile("cp.async.cg.shared.global [%0], [%1], 16;" :: "r"(s), "l"(g) : "memory");
}
static __device__ __forceinline__ void ldsm4(uint32_t r[4], uint32_t a){
    asm volatile("ldmatrix.sync.aligned.m8n8.x4.shared.b16 {%0,%1,%2,%3}, [%4];"
        : "=r"(r[0]),"=r"(r[1]),"=r"(r[2]),"=r"(r[3]) : "r"(a));
}
static __device__ __forceinline__ void ldsm4t(uint32_t r[4], uint32_t a){
    asm volatile("ldmatrix.sync.aligned.m8n8.x4.trans.shared.b16 {%0,%1,%2,%3}, [%4];"
        : "=r"(r[0]),"=r"(r[1]),"=r"(r[2]),"=r"(r[3]) : "r"(a));
}
static __device__ __forceinline__ void mma16(float d[4], const uint32_t a[4], uint32_t b0, uint32_t b1){
    asm volatile("mma.sync.aligned.m16n8k16.row.col.f32.f16.f16.f32 "
        "{%0,%1,%2,%3}, {%4,%5,%6,%7}, {%8,%9}, {%0,%1,%2,%3};"
        : "+f"(d[0]),"+f"(d[1]),"+f"(d[2]),"+f"(d[3])
        : "r"(a[0]),"r"(a[1]),"r"(a[2]),"r"(a[3]),"r"(b0),"r"(b1));
}

// ---------------------------------------------------------------------------
// C[128,128] = A[128,kT].op(B); fp16 in, fp32 accum; 4-stage cp.async ring;
// fragments double-buffered across the two K=16 sub-steps.
// ---------------------------------------------------------------------------
template<bool BNT>
static __device__ __forceinline__ void gemm_run(
    const __half* __restrict__ A, int lda,
    const __half* __restrict__ B, int ldb,
    int kT, float C[4][8][4])
{
    extern __shared__ char smx[];
    const uint32_t sbase = (uint32_t)__cvta_generic_to_shared(smx);
    const int t = threadIdx.x, lane = t & 31, wid = t >> 5;
    const int wm = (wid & 1) * 64, wn = (wid >> 1) * 64;
    const int lrow = (lane & 7) + ((lane >> 3) & 1) * 8;
    const int loct = lane >> 4;
    const int nIt = kT / BK;

    auto issue = [&](int c){
        const int buf = c & (STAGES-1);
        const uint32_t ab = sbase + buf*STAGE_BYTES;
        const uint32_t bb = ab + AS_BYTES;
        const int k0 = c * BK;
        #pragma unroll
        for (int i=0;i<4;i++){
            int f = t + i*NTHR, row = f>>2, seg = f&3;
            cp16(ab + row*(SAH*2) + seg*16, A + (size_t)row*lda + k0 + seg*8);
        }
        #pragma unroll
        for (int i=0;i<4;i++){
            int f = t + i*NTHR;
            if (BNT){
                int row = f>>2, seg = f&3;
                cp16(bb + row*(SBNTH*2) + seg*16, B + (size_t)row*ldb + k0 + seg*8);
            } else {
                int row = f>>4, seg = f&15;
                cp16(bb + row*(SBNNH*2) + seg*16, B + (size_t)(k0+row)*ldb + seg*8);
            }
        }
        asm volatile("cp.async.commit_group;" ::: "memory");
    };

    #pragma unroll
    for (int s=0; s<STAGES-1; s++) issue(s);

    for (int it=0; it<nIt; it++){
        asm volatile("cp.async.wait_group %0;" :: "n"(STAGES-2) : "memory");
        __syncthreads();
        if (it + STAGES-1 < nIt) issue(it + STAGES-1);
        else asm volatile("cp.async.commit_group;" ::: "memory");

        const uint32_t as = sbase + (it & (STAGES-1))*STAGE_BYTES;
        const uint32_t bs = as + AS_BYTES;

        uint32_t af[2][4][4], bf[2][4][4];
        auto ldA = [&](uint32_t f[4][4], int ks){
            #pragma unroll
            for (int mt=0; mt<4; mt++)
                ldsm4(f[mt], as + (wm + mt*16 + lrow)*(SAH*2) + (ks*16 + loct*8)*2);
        };
        auto ldB = [&](uint32_t f[4][4], int ks){
            #pragma unroll
            for (int n2=0; n2<4; n2++){
                if (BNT)
                    ldsm4(f[n2], bs + (wn + n2*16 + lrow)*(SBNTH*2) + (ks*16 + loct*8)*2);
                else
                    ldsm4t(f[n2], bs + (ks*16 + lrow)*(SBNNH*2) + (wn + n2*16 + loct*8)*2);
            }
        };

        ldA(af[0], 0); ldB(bf[0], 0);
        #pragma unroll
        for (int ks=0; ks<2; ks++){
            if (ks == 0){ ldA(af[1], 1); ldB(bf[1], 1); }  // in flight over ks=0 MMAs
            #pragma unroll
            for (int mt=0; mt<4; mt++)
                #pragma unroll
                for (int nt=0; nt<8; nt++){
                    const int n2 = nt>>1, od = nt&1;
                    uint32_t b0 = BNT ? bf[ks][n2][od]   : bf[ks][n2][od*2];
                    uint32_t b1 = BNT ? bf[ks][n2][2+od] : bf[ks][n2][od*2+1];
                    mma16(C[mt][nt], af[ks][mt], b0, b1);
                }
        }
    }
}

static __device__ __forceinline__ void epilogue_h(__half* D, int ldd, float C[4][8][4], float scale)
{
    const int lane = threadIdx.x & 31, wid = threadIdx.x >> 5;
    const int g = lane>>2, tg = lane&3;
    const int wm = (wid&1)*64, wn = (wid>>1)*64;
    #pragma unroll
    for (int mt=0; mt<4; mt++)
        #pragma unroll
        for (int nt=0; nt<8; nt++){
            const int r0 = wm+mt*16+g, c0 = wn+nt*8+2*tg;
            __half2 v0 = __floats2half2_rn(C[mt][nt][0]*scale, C[mt][nt][1]*scale);
            __half2 v1 = __floats2half2_rn(C[mt][nt][2]*scale, C[mt][nt][3]*scale);
            *(__half2*)&D[(size_t)r0*ldd + c0]     = v0;
            *(__half2*)&D[(size_t)(r0+8)*ldd + c0] = v1;
        }
}
static __device__ __forceinline__ void epilogue_f(float* D, int ldd, float C[4][8][4])
{
    const int lane = threadIdx.x & 31, wid = threadIdx.x >> 5;
    const int g = lane>>2, tg = lane&3;
    const int wm = (wid&1)*64, wn = (wid>>1)*64;
    #pragma unroll
    for (int mt=0; mt<4; mt++)
        #pragma unroll
        for (int nt=0; nt<8; nt++){
            const int r0 = wm+mt*16+g, c0 = wn+nt*8+2*tg;
            *(float2*)&D[(size_t)r0*ldd + c0]     = make_float2(C[mt][nt][0], C[mt][nt][1]);
            *(float2*)&D[(size_t)(r0+8)*ldd + c0] = make_float2(C[mt][nt][2], C[mt][nt][3]);
        }
}
// out epilogue with per-row scale (deferred softmax normalization)
static __device__ __forceinline__ void epilogue_fs(float* D, int ldd, float C[4][8][4],
                                                   const float* __restrict__ invRow)
{
    const int lane = threadIdx.x & 31, wid = threadIdx.x >> 5;
    const int g = lane>>2, tg = lane&3;
    const int wm = (wid&1)*64, wn = (wid>>1)*64;
    float iv0[4], iv1[4];
    #pragma unroll
    for (int mt=0; mt<4; mt++){ iv0[mt] = invRow[wm+mt*16+g]; iv1[mt] = invRow[wm+mt*16+g+8]; }
    #pragma unroll
    for (int mt=0; mt<4; mt++)
        #pragma unroll
        for (int nt=0; nt<8; nt++){
            const int r0 = wm+mt*16+g, c0 = wn+nt*8+2*tg;
            *(float2*)&D[(size_t)r0*ldd + c0]     = make_float2(C[mt][nt][0]*iv0[mt], C[mt][nt][1]*iv0[mt]);
            *(float2*)&D[(size_t)(r0+8)*ldd + c0] = make_float2(C[mt][nt][2]*iv1[mt], C[mt][nt][3]*iv1[mt]);
        }
}

// ---------------------------------------------------------------------------
__global__ void __launch_bounds__(256) cvt_k(
    const float4* __restrict__ x, const float4* __restrict__ Wq,
    const float4* __restrict__ Wk, const float4* __restrict__ Wv)
{
    const int nx4 = MTOT*DM/4, nw4 = DM*DM/4;
    int i = blockIdx.x*256 + threadIdx.x;
    const float4* src; __half* dst; int idx;
    if (i < nx4){ src = x; dst = g_X; idx = i; }
    else {
        int j = i - nx4;
        int w = j / nw4; idx = j - w*nw4;
        src = (w==0) ? Wq : (w==1) ? Wk : Wv;
        dst = g_W + (size_t)w*DM*DM;
    }
    float4 v = src[idx];
    __half2 h0 = __floats2half2_rn(v.x, v.y);
    __half2 h1 = __floats2half2_rn(v.z, v.w);
    ((uint2*)dst)[idx] = make_uint2(*(uint32_t*)&h0, *(uint32_t*)&h1);
}

__global__ void __launch_bounds__(NTHR,2) qkv_k()
{
    const int m0 = blockIdx.y*TM, n0 = blockIdx.x*TN;
    const __half* W = g_W + (size_t)blockIdx.z*DM*DM;
    __half*      Cd = (blockIdx.z==0) ? g_Q : (blockIdx.z==1) ? g_K : g_V;
    const float scale = (blockIdx.z==0) ? rsqrtf((float)DM) : 1.0f;

    float C[4][8][4] = {};
    gemm_run<true>(g_X + (size_t)m0*DM, DM, W + (size_t)n0*DM, DM, DM, C);
    epilogue_h(Cd + (size_t)m0*DM + n0, DM, C, scale);
}

__global__ void __launch_bounds__(NTHR,2) scores_k()
{
    const int b = blockIdx.y;
    int i = blockIdx.x;
    int m = (int)((sqrtf(8.0f*i + 1.0f) - 1.0f) * 0.5f);
    while ((m+1)*(m+2)/2 <= i) ++m;
    while (m*(m+1)/2 > i) --m;
    const int n = i - m*(m+1)/2;
    const int m0 = m*TM, n0 = n*TN;

    float C[4][8][4] = {};
    gemm_run<true>(g_Q + ((size_t)b*SEQL + m0)*DM, DM,
                   g_K + ((size_t)b*SEQL + n0)*DM, DM, DM, C);
    epilogue_f(g_S + (size_t)b*SEQL*SEQL + (size_t)m0*SEQL + n0, SEQL, C);
}

// pass1: max (no exp). pass2: exp+sum, store UNNORMALIZED fp16 P; inv -> g_Inv.
__global__ void __launch_bounds__(256) softmax_k()
{
    const int rowg = blockIdx.x;
    const int b = rowg / SEQL, r = rowg % SEQL;
    const float* S = g_S + (size_t)b*SEQL*SEQL + (size_t)r*SEQL;
    __half*     P  = g_P + (size_t)b*SEQL*SEQL + (size_t)r*SEQL;
    const int len = r + 1, t = threadIdx.x, lane = t & 31, wrp = t >> 5;
    __shared__ float red[8];

    float m = -3.4e38f;
    for (int j = t; j < len; j += 256) m = fmaxf(m, S[j]);
    #pragma unroll
    for (int o = 16; o > 0; o >>= 1) m = fmaxf(m, __shfl_xor_sync(0xffffffffu, m, o));
    if (lane == 0) red[wrp] = m;
    __syncthreads();
    m = fmaxf(fmaxf(fmaxf(red[0],red[1]),fmaxf(red[2],red[3])),
              fmaxf(fmaxf(red[4],red[5]),fmaxf(red[6],red[7])));

    float s = 0.0f;
    for (int j = t; j < len; j += 256){
        float e = __expf(S[j] - m);
        P[j] = __float2half_rn(e);
        s += e;
    }
    #pragma unroll
    for (int o = 16; o > 0; o >>= 1) s += __shfl_xor_sync(0xffffffffu, s, o);
    __syncthreads();               // red[] reuse
    if (lane == 0) red[wrp] = s;
    __syncthreads();
    if (t == 0){
        float tot = red[0]+red[1]+red[2]+red[3]+red[4]+red[5]+red[6]+red[7];
        g_Inv[rowg] = 1.0f / tot;
    }

    const int blockend = ((r / TM) + 1) * TM;
    for (int j = len + t; j < blockend; j += 256) P[j] = __float2half_rn(0.0f);
}

__global__ void __launch_bounds__(NTHR,2) out_k(float* __restrict__ out)
{
    const int b = blockIdx.z;
    const int m0 = (gridDim.y-1-blockIdx.y)*TM, n0 = blockIdx.x*TN;
    float C[4][8][4] = {};
    gemm_run<false>(g_P + (size_t)b*SEQL*SEQL + (size_t)m0*SEQL, SEQL,
                    g_V + (size_t)b*SEQL*DM + n0, DM, m0 + TM, C);
    epilogue_fs(out + ((size_t)b*SEQL + m0)*DM + n0, DM, C, g_Inv + b*SEQL + m0);
}

// ---------------------------------------------------------------------------
extern "C" void kernel_launch(void* const* d_in, const int* in_sizes, int n_in,
                              void* d_out, int out_size)
{
    const float* x  = (const float*)d_in[0];
    const float* Wq = (const float*)d_in[1];
    const float* Wk = (const float*)d_in[2];
    const float* Wv = (const float*)d_in[3];
    float* out = (float*)d_out;

    static int inited = 0;
    if (!inited){
        cudaFuncSetAttribute(qkv_k,    cudaFuncAttributeMaxDynamicSharedMemorySize, SMEM_TOTAL);
        cudaFuncSetAttribute(scores_k, cudaFuncAttributeMaxDynamicSharedMemorySize, SMEM_TOTAL);
        cudaFuncSetAttribute(out_k,    cudaFuncAttributeMaxDynamicSharedMemorySize, SMEM_TOTAL);
        inited = 1;
    }

    const int ntot4 = (MTOT*DM + 3*DM*DM)/4;
    cvt_k<<<(ntot4+255)/256, 256>>>((const float4*)x, (const float4*)Wq,
                                    (const float4*)Wk, (const float4*)Wv);

    qkv_k   <<<dim3(DM/TN, MTOT/TM, 3),  NTHR, SMEM_TOTAL>>>();
    scores_k<<<dim3(136, NB),            NTHR, SMEM_TOTAL>>>();
    softmax_k<<<MTOT, 256>>>();
    out_k   <<<dim3(DM/TN, SEQL/TM, NB), NTHR, SMEM_TOTAL>>>(out);
}

// round 8
// speedup vs baseline: 6.5822x; 1.0811x over previous
#include <cuda_runtime.h>
#include <cuda_fp16.h>
#include <stdint.h>

#define SEQL 2048
#define NB   4
#define DM   768
#define MTOT (NB*SEQL)

#define TM 128
#define TN 128
#define BK 32
#define NTHR 128
#define SAH   40
#define SBNTH 40
#define SBNNH 136
#define STAGES 4
#define AS_BYTES (TM*SAH*2)
#define BS_BYTES (TN*SBNTH*2)
#define STAGE_BYTES (AS_BYTES + BS_BYTES)
#define SMEM_TOTAL (STAGES*STAGE_BYTES)   // 81920

#define NMT (SEQL/TM)    // 16 m-tiles per batch

__device__ __half g_X[(size_t)MTOT*DM];
__device__ __half g_W[(size_t)3*DM*DM];
__device__ __half g_Q[(size_t)MTOT*DM];
__device__ __half g_K[(size_t)MTOT*DM];
__device__ __half g_V[(size_t)MTOT*DM];
__device__ __half g_P[(size_t)NB*SEQL*SEQL];
// per-tile partial row sums of exp(S): [b][mt][nt][half][128]
__device__ float  g_PS[(size_t)NB*NMT*NMT*2*128];

static __device__ __forceinline__ void cp16(uint32_t s, const void* g){
    asm volatile("cp.async.cg.shared.global [%0], [%1], 16;" :: "r"(s), "l"(g) : "memory");
}
static __device__ __forceinline__ void ldsm4(uint32_t r[4], uint32_t a){
    asm volatile("ldmatrix.sync.aligned.m8n8.x4.shared.b16 {%0,%1,%2,%3}, [%4];"
        : "=r"(r[0]),"=r"(r[1]),"=r"(r[2]),"=r"(r[3]) : "r"(a));
}
static __device__ __forceinline__ void ldsm4t(uint32_t r[4], uint32_t a){
    asm volatile("ldmatrix.sync.aligned.m8n8.x4.trans.shared.b16 {%0,%1,%2,%3}, [%4];"
        : "=r"(r[0]),"=r"(r[1]),"=r"(r[2]),"=r"(r[3]) : "r"(a));
}
static __device__ __forceinline__ void mma16(float d[4], const uint32_t a[4], uint32_t b0, uint32_t b1){
    asm volatile("mma.sync.aligned.m16n8k16.row.col.f32.f16.f16.f32 "
        "{%0,%1,%2,%3}, {%4,%5,%6,%7}, {%8,%9}, {%0,%1,%2,%3};"
        : "+f"(d[0]),"+f"(d[1]),"+f"(d[2]),"+f"(d[3])
        : "r"(a[0]),"r"(a[1]),"r"(a[2]),"r"(a[3]),"r"(b0),"r"(b1));
}

// ---------------------------------------------------------------------------
template<bool BNT>
static __device__ __forceinline__ void gemm_run(
    const __half* __restrict__ A, int lda,
    const __half* __restrict__ B, int ldb,
    int kT, float C[4][8][4])
{
    extern __shared__ char smx[];
    const uint32_t sbase = (uint32_t)__cvta_generic_to_shared(smx);
    const int t = threadIdx.x, lane = t & 31, wid = t >> 5;
    const int wm = (wid & 1) * 64, wn = (wid >> 1) * 64;
    const int lrow = (lane & 7) + ((lane >> 3) & 1) * 8;
    const int loct = lane >> 4;
    const int nIt = kT / BK;

    auto issue = [&](int c){
        const int buf = c & (STAGES-1);
        const uint32_t ab = sbase + buf*STAGE_BYTES;
        const uint32_t bb = ab + AS_BYTES;
        const int k0 = c * BK;
        #pragma unroll
        for (int i=0;i<4;i++){
            int f = t + i*NTHR, row = f>>2, seg = f&3;
            cp16(ab + row*(SAH*2) + seg*16, A + (size_t)row*lda + k0 + seg*8);
        }
        #pragma unroll
        for (int i=0;i<4;i++){
            int f = t + i*NTHR;
            if (BNT){
                int row = f>>2, seg = f&3;
                cp16(bb + row*(SBNTH*2) + seg*16, B + (size_t)row*ldb + k0 + seg*8);
            } else {
                int row = f>>4, seg = f&15;
                cp16(bb + row*(SBNNH*2) + seg*16, B + (size_t)(k0+row)*ldb + seg*8);
            }
        }
        asm volatile("cp.async.commit_group;" ::: "memory");
    };

    #pragma unroll
    for (int s=0; s<STAGES-1; s++) issue(s);

    for (int it=0; it<nIt; it++){
        asm volatile("cp.async.wait_group %0;" :: "n"(STAGES-2) : "memory");
        __syncthreads();
        if (it + STAGES-1 < nIt) issue(it + STAGES-1);
        else asm volatile("cp.async.commit_group;" ::: "memory");

        const uint32_t as = sbase + (it & (STAGES-1))*STAGE_BYTES;
        const uint32_t bs = as + AS_BYTES;

        uint32_t af[2][4][4], bf[2][4][4];
        auto ldA = [&](uint32_t f[4][4], int ks){
            #pragma unroll
            for (int mt=0; mt<4; mt++)
                ldsm4(f[mt], as + (wm + mt*16 + lrow)*(SAH*2) + (ks*16 + loct*8)*2);
        };
        auto ldB = [&](uint32_t f[4][4], int ks){
            #pragma unroll
            for (int n2=0; n2<4; n2++){
                if (BNT)
                    ldsm4(f[n2], bs + (wn + n2*16 + lrow)*(SBNTH*2) + (ks*16 + loct*8)*2);
                else
                    ldsm4t(f[n2], bs + (ks*16 + lrow)*(SBNNH*2) + (wn + n2*16 + loct*8)*2);
            }
        };

        ldA(af[0], 0); ldB(bf[0], 0);
        #pragma unroll
        for (int ks=0; ks<2; ks++){
            if (ks == 0){ ldA(af[1], 1); ldB(bf[1], 1); }
            #pragma unroll
            for (int mt=0; mt<4; mt++)
                #pragma unroll
                for (int nt=0; nt<8; nt++){
                    const int n2 = nt>>1, od = nt&1;
                    uint32_t b0 = BNT ? bf[ks][n2][od]   : bf[ks][n2][od*2];
                    uint32_t b1 = BNT ? bf[ks][n2][2+od] : bf[ks][n2][od*2+1];
                    mma16(C[mt][nt], af[ks][mt], b0, b1);
                }
        }
    }
}

static __device__ __forceinline__ void epilogue_h(__half* D, int ldd, float C[4][8][4], float scale)
{
    const int lane = threadIdx.x & 31, wid = threadIdx.x >> 5;
    const int g = lane>>2, tg = lane&3;
    const int wm = (wid&1)*64, wn = (wid>>1)*64;
    #pragma unroll
    for (int mt=0; mt<4; mt++)
        #pragma unroll
        for (int nt=0; nt<8; nt++){
            const int r0 = wm+mt*16+g, c0 = wn+nt*8+2*tg;
            __half2 v0 = __floats2half2_rn(C[mt][nt][0]*scale, C[mt][nt][1]*scale);
            __half2 v1 = __floats2half2_rn(C[mt][nt][2]*scale, C[mt][nt][3]*scale);
            *(__half2*)&D[(size_t)r0*ldd + c0]     = v0;
            *(__half2*)&D[(size_t)(r0+8)*ldd + c0] = v1;
        }
}

// scores epilogue: P = exp(S) (causal-masked on diag tiles), fp16; emit
// per-row partial sums (deterministic, shuffle-reduced, one store/row/warp).
static __device__ __forceinline__ void epilogue_p(
    __half* D, int ldd, float C[4][8][4], bool diag, float* __restrict__ psum)
{
    const int lane = threadIdx.x & 31, wid = threadIdx.x >> 5;
    const int g = lane>>2, tg = lane&3;
    const int wm = (wid&1)*64, wn = (wid>>1)*64;
    float rs[4][2] = {};
    #pragma unroll
    for (int mt=0; mt<4; mt++)
        #pragma unroll
        for (int nt=0; nt<8; nt++){
            const int r0 = wm+mt*16+g, c0 = wn+nt*8+2*tg;
            float e0 = __expf(C[mt][nt][0]), e1 = __expf(C[mt][nt][1]);
            float e2 = __expf(C[mt][nt][2]), e3 = __expf(C[mt][nt][3]);
            if (diag){   // local mask: col <= row within the 128x128 tile
                if (c0   > r0  ) e0 = 0.0f;
                if (c0+1 > r0  ) e1 = 0.0f;
                if (c0   > r0+8) e2 = 0.0f;
                if (c0+1 > r0+8) e3 = 0.0f;
            }
            *(__half2*)&D[(size_t)r0*ldd + c0]     = __floats2half2_rn(e0, e1);
            *(__half2*)&D[(size_t)(r0+8)*ldd + c0] = __floats2half2_rn(e2, e3);
            rs[mt][0] += e0 + e1;
            rs[mt][1] += e2 + e3;
        }
    #pragma unroll
    for (int mt=0; mt<4; mt++)
        #pragma unroll
        for (int h=0; h<2; h++){
            float v = rs[mt][h];
            v += __shfl_xor_sync(0xffffffffu, v, 1);
            v += __shfl_xor_sync(0xffffffffu, v, 2);
            if (tg == 0)
                psum[(wid>>1)*128 + wm + mt*16 + h*8 + g] = v;
        }
}

// out epilogue with per-row inv from SMEM
static __device__ __forceinline__ void epilogue_fs(float* D, int ldd, float C[4][8][4],
                                                   const float* __restrict__ sInv)
{
    const int lane = threadIdx.x & 31, wid = threadIdx.x >> 5;
    const int g = lane>>2, tg = lane&3;
    const int wm = (wid&1)*64, wn = (wid>>1)*64;
    #pragma unroll
    for (int mt=0; mt<4; mt++){
        const float iv0 = sInv[wm+mt*16+g], iv1 = sInv[wm+mt*16+g+8];
        #pragma unroll
        for (int nt=0; nt<8; nt++){
            const int r0 = wm+mt*16+g, c0 = wn+nt*8+2*tg;
            *(float2*)&D[(size_t)r0*ldd + c0]     = make_float2(C[mt][nt][0]*iv0, C[mt][nt][1]*iv0);
            *(float2*)&D[(size_t)(r0+8)*ldd + c0] = make_float2(C[mt][nt][2]*iv1, C[mt][nt][3]*iv1);
        }
    }
}

// ---------------------------------------------------------------------------
__global__ void __launch_bounds__(256) cvt_k(
    const float4* __restrict__ x, const float4* __restrict__ Wq,
    const float4* __restrict__ Wk, const float4* __restrict__ Wv)
{
    const int nx4 = MTOT*DM/4, nw4 = DM*DM/4;
    int i = blockIdx.x*256 + threadIdx.x;
    const float4* src; __half* dst; int idx;
    if (i < nx4){ src = x; dst = g_X; idx = i; }
    else {
        int j = i - nx4;
        int w = j / nw4; idx = j - w*nw4;
        src = (w==0) ? Wq : (w==1) ? Wk : Wv;
        dst = g_W + (size_t)w*DM*DM;
    }
    float4 v = src[idx];
    __half2 h0 = __floats2half2_rn(v.x, v.y);
    __half2 h1 = __floats2half2_rn(v.z, v.w);
    ((uint2*)dst)[idx] = make_uint2(*(uint32_t*)&h0, *(uint32_t*)&h1);
}

__global__ void __launch_bounds__(NTHR,2) qkv_k()
{
    const int m0 = blockIdx.y*TM, n0 = blockIdx.x*TN;
    const __half* W = g_W + (size_t)blockIdx.z*DM*DM;
    __half*      Cd = (blockIdx.z==0) ? g_Q : (blockIdx.z==1) ? g_K : g_V;
    const float scale = (blockIdx.z==0) ? rsqrtf((float)DM) : 1.0f;

    float C[4][8][4] = {};
    gemm_run<true>(g_X + (size_t)m0*DM, DM, W + (size_t)n0*DM, DM, DM, C);
    epilogue_h(Cd + (size_t)m0*DM + n0, DM, C, scale);
}

// fused scores + exp + mask + partial row sums
__global__ void __launch_bounds__(NTHR,2) scores_k()
{
    const int b = blockIdx.y;
    int i = blockIdx.x;
    int m = (int)((sqrtf(8.0f*i + 1.0f) - 1.0f) * 0.5f);
    while ((m+1)*(m+2)/2 <= i) ++m;
    while (m*(m+1)/2 > i) --m;
    const int n = i - m*(m+1)/2;
    const int m0 = m*TM, n0 = n*TN;

    float C[4][8][4] = {};
    gemm_run<true>(g_Q + ((size_t)b*SEQL + m0)*DM, DM,
                   g_K + ((size_t)b*SEQL + n0)*DM, DM, DM, C);
    epilogue_p(g_P + (size_t)b*SEQL*SEQL + (size_t)m0*SEQL + n0, SEQL, C,
               (m == n),
               g_PS + ((size_t)(b*NMT + m)*NMT + n)*256);
}

__global__ void __launch_bounds__(NTHR,2) out_k(float* __restrict__ out)
{
    const int b = blockIdx.z;
    const int mt = gridDim.y-1-blockIdx.y;         // largest K first
    const int m0 = mt*TM, n0 = blockIdx.x*TN;

    __shared__ float sInv[128];
    {   // reduce partial row sums -> 1/sum  (128 threads, one row each)
        const int r = threadIdx.x;
        const float* ps = g_PS + (size_t)(b*NMT + mt)*NMT*256;
        float s = 0.0f;
        for (int nt=0; nt<=mt; nt++)
            s += ps[nt*256 + r] + ps[nt*256 + 128 + r];
        sInv[r] = 1.0f / s;
    }
    __syncthreads();

    float C[4][8][4] = {};
    gemm_run<false>(g_P + (size_t)b*SEQL*SEQL + (size_t)m0*SEQL, SEQL,
                    g_V + (size_t)b*SEQL*DM + n0, DM, m0 + TM, C);
    epilogue_fs(out + ((size_t)b*SEQL + m0)*DM + n0, DM, C, sInv);
}

// ---------------------------------------------------------------------------
extern "C" void kernel_launch(void* const* d_in, const int* in_sizes, int n_in,
                              void* d_out, int out_size)
{
    const float* x  = (const float*)d_in[0];
    const float* Wq = (const float*)d_in[1];
    const float* Wk = (const float*)d_in[2];
    const float* Wv = (const float*)d_in[3];
    float* out = (float*)d_out;

    static int inited = 0;
    if (!inited){
        cudaFuncSetAttribute(qkv_k,    cudaFuncAttributeMaxDynamicSharedMemorySize, SMEM_TOTAL);
        cudaFuncSetAttribute(scores_k, cudaFuncAttributeMaxDynamicSharedMemorySize, SMEM_TOTAL);
        cudaFuncSetAttribute(out_k,    cudaFuncAttributeMaxDynamicSharedMemorySize, SMEM_TOTAL);
        inited = 1;
    }

    const int ntot4 = (MTOT*DM + 3*DM*DM)/4;
    cvt_k<<<(ntot4+255)/256, 256>>>((const float4*)x, (const float4*)Wq,
                                    (const float4*)Wk, (const float4*)Wv);

    qkv_k   <<<dim3(DM/TN, MTOT/TM, 3),  NTHR, SMEM_TOTAL>>>();
    scores_k<<<dim3(136, NB),            NTHR, SMEM_TOTAL>>>();
    out_k   <<<dim3(DM/TN, SEQL/TM, NB), NTHR, SMEM_TOTAL>>>(out);
}